// round 3
// baseline (speedup 1.0000x reference)
#include <cuda_runtime.h>
#include <cuda_bf16.h>

// Problem constants
#define BB 16
#define NN 2048
#define DIN 128
#define DQ 64

// Scratch for projected queries/keys: [B][N][DQ] each, fp32 (8 MB each).
__device__ float g_Q[BB * NN * DQ];
__device__ float g_K[BB * NN * DQ];

// ---------------------------------------------------------------------------
// Kernel 1: projections.  queries = x @ Wq^T + bq ; keys = x @ Wk^T + bk
// Block: 256 threads, 32 rows of x per block. Grid: B*N/32 = 1024.
// smem: x tile [32][128] + combined transposed W [128][129-pitch]
// ---------------------------------------------------------------------------
__global__ void proj_kernel(const float* __restrict__ x,
                            const float* __restrict__ Wq,
                            const float* __restrict__ bq,
                            const float* __restrict__ Wk,
                            const float* __restrict__ bk) {
    extern __shared__ float sm[];
    float* x_s  = sm;                 // 32*128 = 4096 floats
    float* Wt_s = sm + 32 * DIN;      // 128 * 129 floats; Wt_s[d][c], c<64: Wq, c>=64: Wk

    const int tid = threadIdx.x;
    const int rowbase = blockIdx.x * 32;   // global row in [0, B*N)

    // Load W transposed: Wq[c][d] -> Wt_s[d*129 + c]
    for (int i = tid; i < DQ * DIN; i += 256) {
        int c = i >> 7;          // 0..63
        int d = i & 127;
        Wt_s[d * 129 + c] = Wq[i];
    }
    for (int i = tid; i < DQ * DIN; i += 256) {
        int c = i >> 7;
        int d = i & 127;
        Wt_s[d * 129 + 64 + c] = Wk[i];
    }
    // Load x tile
    for (int i = tid; i < 32 * DIN; i += 256) {
        x_s[i] = x[rowbase * DIN + i];
    }
    __syncthreads();

    const int c  = tid & 127;   // output column 0..127 (Q cols 0..63, K cols 64..127)
    const int rh = tid >> 7;    // 0 or 1

    for (int r = rh; r < 32; r += 2) {
        float acc = 0.0f;
        const float* xr = &x_s[r * DIN];
        #pragma unroll 8
        for (int d = 0; d < DIN; d++) {
            acc += xr[d] * Wt_s[d * 129 + c];
        }
        const int row = rowbase + r;
        if (c < DQ) {
            g_Q[row * DQ + c] = acc + bq[c];
        } else {
            g_K[row * DQ + (c - DQ)] = acc + bk[c - DQ];
        }
    }
}

// ---------------------------------------------------------------------------
// Kernel 2: flash-style masked attention aggregation.
//   scores[n,m] = (K[n] . Q[m]) * 1/8 + neg[m];  weights = softmax_m;  out = w @ x
// Block: 256 threads (8 warps), 16 key-rows per block (2 rows per warp).
// Stream over m in tiles of 128. Grid: (N/16, B).
// ---------------------------------------------------------------------------
#define ROWS 16
#define MT 128

__global__ void attn_kernel(const float* __restrict__ x,
                            const int* __restrict__ mask,
                            float* __restrict__ out) {
    extern __shared__ float sm[];
    float* Qt_s  = sm;                       // 64 * 129
    float* x_s   = Qt_s + DQ * 129;          // 128 * 128 (16B-aligned: 8256*4 % 16 == 0)
    float* K_s   = x_s + MT * DIN;           // 16 * 64
    float* p_s   = K_s + ROWS * DQ;          // 16 * 128
    float* neg_s = p_s + ROWS * MT;          // 128

    const int tid  = threadIdx.x;
    const int warp = tid >> 5;
    const int lane = tid & 31;
    const int b    = blockIdx.y;
    const int rowbase = blockIdx.x * ROWS;   // key-row base within batch

    // Load K rows for this block (contiguous in g_K)
    for (int i = tid; i < ROWS * DQ; i += 256) {
        K_s[i] = g_K[(b * NN + rowbase) * DQ + i];
    }

    const int r0 = warp * 2;
    const int r1 = warp * 2 + 1;

    float rm0 = -1e30f, rm1 = -1e30f;   // running max
    float rl0 = 0.0f,  rl1 = 0.0f;      // running sum
    float acc0[4] = {0.f, 0.f, 0.f, 0.f};
    float acc1[4] = {0.f, 0.f, 0.f, 0.f};

    const float* xb = x + (size_t)b * NN * DIN;

    for (int t = 0; t < NN / MT; t++) {
        const int mbase = t * MT;
        __syncthreads();
        // Load Q tile transposed: Q[m][d] -> Qt_s[d*129 + m]
        for (int i = tid; i < MT * DQ; i += 256) {
            int m = i >> 6;
            int d = i & 63;
            Qt_s[d * 129 + m] = g_Q[(b * NN + mbase) * DQ + i];
        }
        // Load x tile (float4)
        {
            const float4* src = (const float4*)(xb + mbase * DIN);
            float4* dst = (float4*)x_s;
            for (int i = tid; i < MT * DIN / 4; i += 256) dst[i] = src[i];
        }
        // mask -> additive neg
        if (tid < MT) {
            neg_s[tid] = (mask[b * NN + mbase + tid] > 0) ? 0.0f : -1e9f;
        }
        __syncthreads();

        // ---- scores: each lane computes 4 m-positions for 2 rows ----
        float s00 = 0.f, s01 = 0.f, s02 = 0.f, s03 = 0.f;
        float s10 = 0.f, s11 = 0.f, s12 = 0.f, s13 = 0.f;
        const float* k0p = &K_s[r0 * DQ];
        const float* k1p = &K_s[r1 * DQ];
        #pragma unroll 4
        for (int d = 0; d < DQ; d++) {
            const float k0 = k0p[d];
            const float k1 = k1p[d];
            const float* qrow = &Qt_s[d * 129];
            const float q0 = qrow[lane];
            const float q1 = qrow[lane + 32];
            const float q2 = qrow[lane + 64];
            const float q3 = qrow[lane + 96];
            s00 += k0 * q0; s01 += k0 * q1; s02 += k0 * q2; s03 += k0 * q3;
            s10 += k1 * q0; s11 += k1 * q1; s12 += k1 * q2; s13 += k1 * q3;
        }
        const float scale = 0.125f;  // 1/sqrt(64)
        const float n0 = neg_s[lane], n1 = neg_s[lane + 32];
        const float n2 = neg_s[lane + 64], n3 = neg_s[lane + 96];
        s00 = s00 * scale + n0; s01 = s01 * scale + n1;
        s02 = s02 * scale + n2; s03 = s03 * scale + n3;
        s10 = s10 * scale + n0; s11 = s11 * scale + n1;
        s12 = s12 * scale + n2; s13 = s13 * scale + n3;

        // ---- online softmax row 0 ----
        {
            float tmax = fmaxf(fmaxf(s00, s01), fmaxf(s02, s03));
            #pragma unroll
            for (int o = 16; o > 0; o >>= 1)
                tmax = fmaxf(tmax, __shfl_xor_sync(0xffffffffu, tmax, o));
            const float nm = fmaxf(rm0, tmax);
            const float corr = __expf(rm0 - nm);
            const float p0 = __expf(s00 - nm);
            const float p1 = __expf(s01 - nm);
            const float p2 = __expf(s02 - nm);
            const float p3 = __expf(s03 - nm);
            float tsum = p0 + p1 + p2 + p3;
            #pragma unroll
            for (int o = 16; o > 0; o >>= 1)
                tsum += __shfl_xor_sync(0xffffffffu, tsum, o);
            rl0 = rl0 * corr + tsum;
            rm0 = nm;
            acc0[0] *= corr; acc0[1] *= corr; acc0[2] *= corr; acc0[3] *= corr;
            p_s[r0 * MT + lane]      = p0;
            p_s[r0 * MT + lane + 32] = p1;
            p_s[r0 * MT + lane + 64] = p2;
            p_s[r0 * MT + lane + 96] = p3;
        }
        // ---- online softmax row 1 ----
        {
            float tmax = fmaxf(fmaxf(s10, s11), fmaxf(s12, s13));
            #pragma unroll
            for (int o = 16; o > 0; o >>= 1)
                tmax = fmaxf(tmax, __shfl_xor_sync(0xffffffffu, tmax, o));
            const float nm = fmaxf(rm1, tmax);
            const float corr = __expf(rm1 - nm);
            const float p0 = __expf(s10 - nm);
            const float p1 = __expf(s11 - nm);
            const float p2 = __expf(s12 - nm);
            const float p3 = __expf(s13 - nm);
            float tsum = p0 + p1 + p2 + p3;
            #pragma unroll
            for (int o = 16; o > 0; o >>= 1)
                tsum += __shfl_xor_sync(0xffffffffu, tsum, o);
            rl1 = rl1 * corr + tsum;
            rm1 = nm;
            acc1[0] *= corr; acc1[1] *= corr; acc1[2] *= corr; acc1[3] *= corr;
            p_s[r1 * MT + lane]      = p0;
            p_s[r1 * MT + lane + 32] = p1;
            p_s[r1 * MT + lane + 64] = p2;
            p_s[r1 * MT + lane + 96] = p3;
        }
        __syncwarp();

        // ---- accumulate: acc[d] += sum_m p[m] * x[m][d], lane owns dims lane*4..+3 ----
        const float4* xv4 = (const float4*)x_s;
        const float* pr0 = &p_s[r0 * MT];
        const float* pr1 = &p_s[r1 * MT];
        #pragma unroll 4
        for (int mm = 0; mm < MT; mm++) {
            const float p0 = pr0[mm];
            const float p1 = pr1[mm];
            const float4 xv = xv4[mm * 32 + lane];
            acc0[0] += p0 * xv.x; acc0[1] += p0 * xv.y;
            acc0[2] += p0 * xv.z; acc0[3] += p0 * xv.w;
            acc1[0] += p1 * xv.x; acc1[1] += p1 * xv.y;
            acc1[2] += p1 * xv.z; acc1[3] += p1 * xv.w;
        }
    }

    // ---- finalize ----
    const float inv0 = 1.0f / rl0;
    const float inv1 = 1.0f / rl1;
    float4 o0 = make_float4(acc0[0] * inv0, acc0[1] * inv0, acc0[2] * inv0, acc0[3] * inv0);
    float4 o1 = make_float4(acc1[0] * inv1, acc1[1] * inv1, acc1[2] * inv1, acc1[3] * inv1);
    float4* outp = (float4*)(out + (size_t)(b * NN + rowbase) * DIN);
    outp[r0 * 32 + lane] = o0;
    outp[r1 * 32 + lane] = o1;
}

// ---------------------------------------------------------------------------
extern "C" void kernel_launch(void* const* d_in, const int* in_sizes, int n_in,
                              void* d_out, int out_size) {
    const float* x  = (const float*)d_in[0];
    const int*   mk = (const int*)d_in[1];
    const float* Wq = (const float*)d_in[2];
    const float* bq = (const float*)d_in[3];
    const float* Wk = (const float*)d_in[4];
    const float* bk = (const float*)d_in[5];
    float* out = (float*)d_out;

    static bool attr_set = false;
    const int proj_smem = (32 * DIN + DIN * 129) * 4;                    // 82,432 B
    const int attn_smem = (DQ * 129 + MT * DIN + ROWS * DQ + ROWS * MT + MT) * 4;  // 111,360 B
    if (!attr_set) {
        cudaFuncSetAttribute(proj_kernel, cudaFuncAttributeMaxDynamicSharedMemorySize, proj_smem);
        cudaFuncSetAttribute(attn_kernel, cudaFuncAttributeMaxDynamicSharedMemorySize, attn_smem);
        attr_set = true;
    }

    proj_kernel<<<(BB * NN) / 32, 256, proj_smem>>>(x, Wq, bq, Wk, bk);
    attn_kernel<<<dim3(NN / ROWS, BB), 256, attn_smem>>>(x, mk, out);
}

// round 14
// speedup vs baseline: 2.5956x; 2.5956x over previous
#include <cuda_runtime.h>
#include <cuda_bf16.h>
#include <cstdint>

// Problem constants
#define BB 16
#define NN 2048
#define DIN 128
#define DQ 64
#define CHUNK 128
#define NCHUNK (NN / CHUNK)

// ---------------------------------------------------------------------------
// Scratch (bf16 split representations)
// ---------------------------------------------------------------------------
__device__ __nv_bfloat16 g_Qhi[BB * NN * DQ];
__device__ __nv_bfloat16 g_Qlo[BB * NN * DQ];
__device__ __nv_bfloat16 g_Khi[BB * NN * DQ];
__device__ __nv_bfloat16 g_Klo[BB * NN * DQ];
__device__ __nv_bfloat16 g_xThi[BB * DIN * NN];   // [b][d][m]
__device__ __nv_bfloat16 g_xTlo[BB * DIN * NN];

// ---------------------------------------------------------------------------
// mma.sync m16n8k16 bf16 -> fp32 (standard PTX, works on base sm_103 target)
// ---------------------------------------------------------------------------
__device__ __forceinline__ void mma16816(float* c, const uint32_t* a, const uint32_t* b) {
    asm volatile(
        "mma.sync.aligned.m16n8k16.row.col.f32.bf16.bf16.f32 "
        "{%0,%1,%2,%3}, {%4,%5,%6,%7}, {%8,%9}, {%0,%1,%2,%3};"
        : "+f"(c[0]), "+f"(c[1]), "+f"(c[2]), "+f"(c[3])
        : "r"(a[0]), "r"(a[1]), "r"(a[2]), "r"(a[3]), "r"(b[0]), "r"(b[1]));
}

__device__ __forceinline__ uint32_t pack_bf16(float lo, float hi) {
    return ((uint32_t)__bfloat16_as_ushort(__float2bfloat16(hi)) << 16) |
           (uint32_t)__bfloat16_as_ushort(__float2bfloat16(lo));
}

// smem byte offsets (attn kernel).  K/Q pitch 68 bf16 = 136B; X pitch 132 bf16 = 264B.
#define SA_KH 0
#define SA_KL 17408
#define SA_QH 34816
#define SA_QL 52224
#define SA_XH 69632
#define SA_XL 103424
#define SA_NEG 137216
#define SA_TOTAL 137728

// ---------------------------------------------------------------------------
// Kernel 1: projections -> bf16 hi/lo splits of Q and K
// ---------------------------------------------------------------------------
__global__ void proj_split_kernel(const float* __restrict__ x,
                                  const float* __restrict__ Wq,
                                  const float* __restrict__ bq,
                                  const float* __restrict__ Wk,
                                  const float* __restrict__ bk) {
    extern __shared__ float sm[];
    float* x_s  = sm;             // 32*128
    float* Wt_s = sm + 32 * DIN;  // 128*129

    const int tid = threadIdx.x;
    const int rowbase = blockIdx.x * 32;

    for (int i = tid; i < DQ * DIN; i += 256) {
        int c = i >> 7, d = i & 127;
        Wt_s[d * 129 + c] = Wq[i];
    }
    for (int i = tid; i < DQ * DIN; i += 256) {
        int c = i >> 7, d = i & 127;
        Wt_s[d * 129 + 64 + c] = Wk[i];
    }
    for (int i = tid; i < 32 * DIN; i += 256) x_s[i] = x[rowbase * DIN + i];
    __syncthreads();

    const int c  = tid & 127;
    const int rh = tid >> 7;
    for (int r = rh; r < 32; r += 2) {
        float acc = 0.0f;
        const float* xr = &x_s[r * DIN];
        #pragma unroll 8
        for (int d = 0; d < DIN; d++) acc += xr[d] * Wt_s[d * 129 + c];
        const int row = rowbase + r;
        if (c < DQ) {
            float v = acc + bq[c];
            __nv_bfloat16 h = __float2bfloat16(v);
            g_Qhi[row * DQ + c] = h;
            g_Qlo[row * DQ + c] = __float2bfloat16(v - __bfloat162float(h));
        } else {
            float v = acc + bk[c - DQ];
            __nv_bfloat16 h = __float2bfloat16(v);
            g_Khi[row * DQ + (c - DQ)] = h;
            g_Klo[row * DQ + (c - DQ)] = __float2bfloat16(v - __bfloat162float(h));
        }
    }
}

// ---------------------------------------------------------------------------
// Kernel 2: x -> transposed bf16 hi/lo splits xT[b][d][m]
// ---------------------------------------------------------------------------
__global__ void xt_split_kernel(const float* __restrict__ x) {
    extern __shared__ float sm[];   // [64][129]
    const int tid = threadIdx.x;
    const int b = blockIdx.y;
    const int mbase = blockIdx.x * 64;

    for (int i = tid; i < 64 * DIN; i += 256) {
        int m = i >> 7, d = i & 127;
        sm[m * 129 + d] = x[((size_t)(b * NN + mbase + m)) * DIN + d];
    }
    __syncthreads();
    for (int i = tid; i < DIN * 64; i += 256) {
        int d = i >> 6, mi = i & 63;
        float v = sm[mi * 129 + d];
        __nv_bfloat16 h = __float2bfloat16(v);
        size_t idx = ((size_t)(b * DIN + d)) * NN + mbase + mi;
        g_xThi[idx] = h;
        g_xTlo[idx] = __float2bfloat16(v - __bfloat162float(h));
    }
}

// ---------------------------------------------------------------------------
// Kernel 3: mma.sync flash attention.
// Grid (16 key-blocks, 16 batches), 256 threads = 8 warps.
// Warp w owns key rows [w*16, w*16+16).  Stream 16 query chunks of 128.
// Split-bf16: every product = hi*hi + hi*lo + lo*hi (3 mma).
// ---------------------------------------------------------------------------
__global__ void __launch_bounds__(256, 1)
attn_mma_kernel(const int* __restrict__ mask, float* __restrict__ out) {
    extern __shared__ char smem[];
    char* KH = smem + SA_KH;
    char* KL = smem + SA_KL;
    char* QH = smem + SA_QH;
    char* QL = smem + SA_QL;
    char* XH = smem + SA_XH;
    char* XL = smem + SA_XL;
    float* negp = (float*)(smem + SA_NEG);

    const int tid  = threadIdx.x;
    const int warp = tid >> 5;
    const int lane = tid & 31;
    const int g    = lane >> 2;     // group row 0..7
    const int tig  = lane & 3;      // thread in group
    const int b    = blockIdx.y;
    const int rowbase = blockIdx.x * 128;
    const int wrow = warp * 16;

    // ---- fill K tiles (once): rows [128][64 bf16], pitch 136B ----
    {
        const uint32_t* kh = (const uint32_t*)(g_Khi + (size_t)(b * NN + rowbase) * DQ);
        const uint32_t* kl = (const uint32_t*)(g_Klo + (size_t)(b * NN + rowbase) * DQ);
        for (int i = tid; i < 128 * 32; i += 256) {
            int r = i >> 5, c = i & 31;
            *(uint32_t*)(KH + r * 136 + c * 4) = kh[i];
            *(uint32_t*)(KL + r * 136 + c * 4) = kl[i];
        }
    }
    __syncthreads();

    // ---- preload K A-fragments into registers (reused all chunks) ----
    // A m16k16: a0=(g, c0) a1=(g+8, c0) a2=(g, c0+8) a3=(g+8, c0+8), each reg = 2 bf16 cols
    uint32_t kfh[4][4], kfl[4][4];
    #pragma unroll
    for (int kt = 0; kt < 4; kt++) {
        int r0 = wrow + g, r1 = wrow + g + 8;
        int c0 = kt * 16 + 2 * tig;
        kfh[kt][0] = *(uint32_t*)(KH + r0 * 136 + c0 * 2);
        kfh[kt][1] = *(uint32_t*)(KH + r1 * 136 + c0 * 2);
        kfh[kt][2] = *(uint32_t*)(KH + r0 * 136 + (c0 + 8) * 2);
        kfh[kt][3] = *(uint32_t*)(KH + r1 * 136 + (c0 + 8) * 2);
        kfl[kt][0] = *(uint32_t*)(KL + r0 * 136 + c0 * 2);
        kfl[kt][1] = *(uint32_t*)(KL + r1 * 136 + c0 * 2);
        kfl[kt][2] = *(uint32_t*)(KL + r0 * 136 + (c0 + 8) * 2);
        kfl[kt][3] = *(uint32_t*)(KL + r1 * 136 + (c0 + 8) * 2);
    }

    float o[16][4];
    #pragma unroll
    for (int i = 0; i < 16; i++) { o[i][0] = o[i][1] = o[i][2] = o[i][3] = 0.0f; }
    float rs0 = 0.0f, rs1 = 0.0f;

    for (int t = 0; t < NCHUNK; t++) {
        const int mbase = t * CHUNK;
        __syncthreads();   // protect smem Q/X/neg against previous iteration's readers

        // ---- fill Q chunk [128 q][64 dq], pitch 136B ----
        {
            const uint32_t* qh = (const uint32_t*)(g_Qhi + (size_t)(b * NN + mbase) * DQ);
            const uint32_t* ql = (const uint32_t*)(g_Qlo + (size_t)(b * NN + mbase) * DQ);
            for (int i = tid; i < 128 * 32; i += 256) {
                int r = i >> 5, c = i & 31;
                *(uint32_t*)(QH + r * 136 + c * 4) = qh[i];
                *(uint32_t*)(QL + r * 136 + c * 4) = ql[i];
            }
        }
        // ---- fill Xt chunk [128 d][128 q], pitch 264B ----
        for (int i = tid; i < 128 * 64; i += 256) {
            int d = i >> 6, c = i & 63;
            size_t base = ((size_t)(b * DIN + d)) * NN + mbase;
            *(uint32_t*)(XH + d * 264 + c * 4) = *(const uint32_t*)(g_xThi + base + 2 * c);
            *(uint32_t*)(XL + d * 264 + c * 4) = *(const uint32_t*)(g_xTlo + base + 2 * c);
        }
        if (tid < 128) negp[tid] = (mask[b * NN + mbase + tid] > 0) ? 0.0f : -1e9f;
        __syncthreads();

        // ---- per-warp mainloop: 8 k16 groups of queries ----
        #pragma unroll
        for (int j = 0; j < 8; j++) {
            uint32_t pah[4], pal[4];
            // two n8 S-tiles -> exp -> pack into one m16k16 A fragment pair
            #pragma unroll
            for (int h = 0; h < 2; h++) {
                const int nt = 2 * j + h;
                float c4[4] = {0.f, 0.f, 0.f, 0.f};
                const int qr = nt * 8 + g;
                #pragma unroll
                for (int kt = 0; kt < 4; kt++) {
                    const int cc = kt * 16 + 2 * tig;
                    uint32_t bh[2], bl[2];
                    bh[0] = *(uint32_t*)(QH + qr * 136 + cc * 2);
                    bh[1] = *(uint32_t*)(QH + qr * 136 + (cc + 8) * 2);
                    bl[0] = *(uint32_t*)(QL + qr * 136 + cc * 2);
                    bl[1] = *(uint32_t*)(QL + qr * 136 + (cc + 8) * 2);
                    mma16816(c4, kfh[kt], bh);
                    mma16816(c4, kfh[kt], bl);
                    mma16816(c4, kfl[kt], bh);
                }
                const float n0 = negp[nt * 8 + 2 * tig];
                const float n1 = negp[nt * 8 + 2 * tig + 1];
                float p0 = __expf(c4[0] * 0.125f + n0);
                float p1 = __expf(c4[1] * 0.125f + n1);
                float p2 = __expf(c4[2] * 0.125f + n0);
                float p3 = __expf(c4[3] * 0.125f + n1);
                rs0 += p0 + p1;
                rs1 += p2 + p3;
                // hi parts
                float h0 = __bfloat162float(__float2bfloat16(p0));
                float h1 = __bfloat162float(__float2bfloat16(p1));
                float h2 = __bfloat162float(__float2bfloat16(p2));
                float h3 = __bfloat162float(__float2bfloat16(p3));
                pah[h * 2 + 0] = pack_bf16(h0, h1);         // a0 / a2 : row g
                pah[h * 2 + 1] = pack_bf16(h2, h3);         // a1 / a3 : row g+8
                pal[h * 2 + 0] = pack_bf16(p0 - h0, p1 - h1);
                pal[h * 2 + 1] = pack_bf16(p2 - h2, p3 - h3);
            }
            // O += P @ X : A = P (m16 keys x k16 queries), B = Xt (n8 dims x k16 queries)
            const int q0 = j * 16 + 2 * tig;
            #pragma unroll
            for (int nt2 = 0; nt2 < 16; nt2++) {
                const int xr = nt2 * 8 + g;
                uint32_t bxh[2], bxl[2];
                bxh[0] = *(uint32_t*)(XH + xr * 264 + q0 * 2);
                bxh[1] = *(uint32_t*)(XH + xr * 264 + (q0 + 8) * 2);
                bxl[0] = *(uint32_t*)(XL + xr * 264 + q0 * 2);
                bxl[1] = *(uint32_t*)(XL + xr * 264 + (q0 + 8) * 2);
                mma16816(o[nt2], pah, bxh);
                mma16816(o[nt2], pah, bxl);
                mma16816(o[nt2], pal, bxh);
            }
        }
    }

    // ---- reduce rowsums across the quad (lanes sharing g) ----
    rs0 += __shfl_xor_sync(0xffffffffu, rs0, 1);
    rs0 += __shfl_xor_sync(0xffffffffu, rs0, 2);
    rs1 += __shfl_xor_sync(0xffffffffu, rs1, 1);
    rs1 += __shfl_xor_sync(0xffffffffu, rs1, 2);
    const float inv0 = 1.0f / rs0;
    const float inv1 = 1.0f / rs1;

    // ---- write out: rows wrow+g and wrow+g+8, dims nt2*8 + 2tig (+1) ----
    float* o0p = out + ((size_t)(b * NN + rowbase + wrow + g)) * DIN;
    float* o1p = out + ((size_t)(b * NN + rowbase + wrow + g + 8)) * DIN;
    #pragma unroll
    for (int nt2 = 0; nt2 < 16; nt2++) {
        const int d0 = nt2 * 8 + 2 * tig;
        float2 v0 = make_float2(o[nt2][0] * inv0, o[nt2][1] * inv0);
        float2 v1 = make_float2(o[nt2][2] * inv1, o[nt2][3] * inv1);
        *(float2*)(o0p + d0) = v0;
        *(float2*)(o1p + d0) = v1;
    }
}

// ---------------------------------------------------------------------------
extern "C" void kernel_launch(void* const* d_in, const int* in_sizes, int n_in,
                              void* d_out, int out_size) {
    const float* x  = (const float*)d_in[0];
    const int*   mk = (const int*)d_in[1];
    const float* Wq = (const float*)d_in[2];
    const float* bq = (const float*)d_in[3];
    const float* Wk = (const float*)d_in[4];
    const float* bk = (const float*)d_in[5];
    float* out = (float*)d_out;

    const int proj_smem = (32 * DIN + DIN * 129) * 4;   // 82,432 B
    const int xt_smem   = 64 * 129 * 4;                 // 33,024 B
    const int attn_smem = SA_TOTAL;                     // 137,728 B

    static bool attr_set = false;
    if (!attr_set) {
        cudaFuncSetAttribute(proj_split_kernel, cudaFuncAttributeMaxDynamicSharedMemorySize, proj_smem);
        cudaFuncSetAttribute(xt_split_kernel,   cudaFuncAttributeMaxDynamicSharedMemorySize, xt_smem);
        cudaFuncSetAttribute(attn_mma_kernel,   cudaFuncAttributeMaxDynamicSharedMemorySize, attn_smem);
        attr_set = true;
    }

    proj_split_kernel<<<(BB * NN) / 32, 256, proj_smem>>>(x, Wq, bq, Wk, bk);
    xt_split_kernel<<<dim3(NN / 64, BB), 256, xt_smem>>>(x);
    attn_mma_kernel<<<dim3(NN / 128, BB), 256, attn_smem>>>(mk, out);
}

// round 16
// speedup vs baseline: 3.0041x; 1.1574x over previous
#include <cuda_runtime.h>
#include <cuda_bf16.h>
#include <cstdint>

// Problem constants
#define BB 16
#define NN 2048
#define DIN 128
#define DQ 64
#define CHUNK 128
#define NCHUNK (NN / CHUNK)

// ---------------------------------------------------------------------------
// Scratch (bf16 split representations)
// ---------------------------------------------------------------------------
__device__ __nv_bfloat16 g_Qhi[BB * NN * DQ];
__device__ __nv_bfloat16 g_Qlo[BB * NN * DQ];
__device__ __nv_bfloat16 g_Khi[BB * NN * DQ];
__device__ __nv_bfloat16 g_Klo[BB * NN * DQ];
__device__ __nv_bfloat16 g_xThi[BB * DIN * NN];   // [b][d][m]
__device__ __nv_bfloat16 g_xTlo[BB * DIN * NN];

// ---------------------------------------------------------------------------
// mma.sync m16n8k16 bf16 -> fp32
// ---------------------------------------------------------------------------
__device__ __forceinline__ void mma16816(float* c, const uint32_t* a, const uint32_t* b) {
    asm volatile(
        "mma.sync.aligned.m16n8k16.row.col.f32.bf16.bf16.f32 "
        "{%0,%1,%2,%3}, {%4,%5,%6,%7}, {%8,%9}, {%0,%1,%2,%3};"
        : "+f"(c[0]), "+f"(c[1]), "+f"(c[2]), "+f"(c[3])
        : "r"(a[0]), "r"(a[1]), "r"(a[2]), "r"(a[3]), "r"(b[0]), "r"(b[1]));
}

__device__ __forceinline__ uint32_t pack_bf16(float lo, float hi) {
    return ((uint32_t)__bfloat16_as_ushort(__float2bfloat16(hi)) << 16) |
           (uint32_t)__bfloat16_as_ushort(__float2bfloat16(lo));
}

// smem byte offsets (attn kernel).  K/Q pitch 68 bf16 = 136B; X pitch 132 bf16 = 264B.
#define SA_KH 0
#define SA_KL 17408
#define SA_QH 34816
#define SA_QL 52224
#define SA_XH 69632
#define SA_XL 103424
#define SA_NEG 137216
#define SA_TOTAL 137728

// ---------------------------------------------------------------------------
// Kernel 1 (v2): projections -> bf16 hi/lo splits of Q and K.
// 64 rows/block, 256 threads.  Thread owns output column c and 32 rows.
// Register-blocked: per 4-d chunk, 4 scalar W loads + per-row broadcast
// LDS.128 of x + 4 FFMA.  LDS/thread: 4096 -> 1152.
// ---------------------------------------------------------------------------
__global__ void __launch_bounds__(256)
proj_split_kernel(const float* __restrict__ x,
                  const float* __restrict__ Wq,
                  const float* __restrict__ bq,
                  const float* __restrict__ Wk,
                  const float* __restrict__ bk) {
    extern __shared__ float sm[];
    float* x_s  = sm;                 // 64*128 floats
    float* Wt_s = sm + 64 * DIN;      // 128*129 floats; Wt_s[d*129 + c]

    const int tid = threadIdx.x;
    const int rowbase = blockIdx.x * 64;

    for (int i = tid; i < DQ * DIN; i += 256) {
        int c = i >> 7, d = i & 127;
        Wt_s[d * 129 + c] = Wq[i];
    }
    for (int i = tid; i < DQ * DIN; i += 256) {
        int c = i >> 7, d = i & 127;
        Wt_s[d * 129 + 64 + c] = Wk[i];
    }
    {
        const float4* xs4 = (const float4*)(x + (size_t)rowbase * DIN);
        float4* xd4 = (float4*)x_s;
        for (int i = tid; i < 64 * DIN / 4; i += 256) xd4[i] = xs4[i];
    }
    __syncthreads();

    const int c  = tid & 127;   // output column: 0..63 -> Q, 64..127 -> K
    const int rh = tid >> 7;    // row parity

    float acc[32];
    #pragma unroll
    for (int i = 0; i < 32; i++) acc[i] = 0.0f;

    for (int dd = 0; dd < DIN; dd += 4) {
        const float w0 = Wt_s[(dd + 0) * 129 + c];
        const float w1 = Wt_s[(dd + 1) * 129 + c];
        const float w2 = Wt_s[(dd + 2) * 129 + c];
        const float w3 = Wt_s[(dd + 3) * 129 + c];
        #pragma unroll
        for (int i = 0; i < 32; i++) {
            const int r = 2 * i + rh;
            const float4 xv = *(const float4*)&x_s[r * DIN + dd];
            acc[i] += xv.x * w0 + xv.y * w1 + xv.z * w2 + xv.w * w3;
        }
    }

    const bool isQ = (c < DQ);
    const float bias = isQ ? bq[c] : bk[c - DQ];
    const int cc = isQ ? c : (c - DQ);
    __nv_bfloat16* dst_hi = isQ ? g_Qhi : g_Khi;
    __nv_bfloat16* dst_lo = isQ ? g_Qlo : g_Klo;
    #pragma unroll
    for (int i = 0; i < 32; i++) {
        const int row = rowbase + 2 * i + rh;
        const float v = acc[i] + bias;
        const __nv_bfloat16 h = __float2bfloat16(v);
        dst_hi[row * DQ + cc] = h;
        dst_lo[row * DQ + cc] = __float2bfloat16(v - __bfloat162float(h));
    }
}

// ---------------------------------------------------------------------------
// Kernel 2: x -> transposed bf16 hi/lo splits xT[b][d][m]  (unchanged)
// ---------------------------------------------------------------------------
__global__ void xt_split_kernel(const float* __restrict__ x) {
    extern __shared__ float sm[];   // [64][129]
    const int tid = threadIdx.x;
    const int b = blockIdx.y;
    const int mbase = blockIdx.x * 64;

    for (int i = tid; i < 64 * DIN; i += 256) {
        int m = i >> 7, d = i & 127;
        sm[m * 129 + d] = x[((size_t)(b * NN + mbase + m)) * DIN + d];
    }
    __syncthreads();
    for (int i = tid; i < DIN * 64; i += 256) {
        int d = i >> 6, mi = i & 63;
        float v = sm[mi * 129 + d];
        __nv_bfloat16 h = __float2bfloat16(v);
        size_t idx = ((size_t)(b * DIN + d)) * NN + mbase + mi;
        g_xThi[idx] = h;
        g_xTlo[idx] = __float2bfloat16(v - __bfloat162float(h));
    }
}

// ---------------------------------------------------------------------------
// Kernel 3: mma.sync flash attention (unchanged from R14 — 490us config).
// Grid (16 key-blocks, 16 batches), 256 threads = 8 warps.
// ---------------------------------------------------------------------------
__global__ void __launch_bounds__(256, 1)
attn_mma_kernel(const int* __restrict__ mask, float* __restrict__ out) {
    extern __shared__ char smem[];
    char* KH = smem + SA_KH;
    char* KL = smem + SA_KL;
    char* QH = smem + SA_QH;
    char* QL = smem + SA_QL;
    char* XH = smem + SA_XH;
    char* XL = smem + SA_XL;
    float* negp = (float*)(smem + SA_NEG);

    const int tid  = threadIdx.x;
    const int warp = tid >> 5;
    const int lane = tid & 31;
    const int g    = lane >> 2;
    const int tig  = lane & 3;
    const int b    = blockIdx.y;
    const int rowbase = blockIdx.x * 128;
    const int wrow = warp * 16;

    {
        const uint32_t* kh = (const uint32_t*)(g_Khi + (size_t)(b * NN + rowbase) * DQ);
        const uint32_t* kl = (const uint32_t*)(g_Klo + (size_t)(b * NN + rowbase) * DQ);
        for (int i = tid; i < 128 * 32; i += 256) {
            int r = i >> 5, c = i & 31;
            *(uint32_t*)(KH + r * 136 + c * 4) = kh[i];
            *(uint32_t*)(KL + r * 136 + c * 4) = kl[i];
        }
    }
    __syncthreads();

    uint32_t kfh[4][4], kfl[4][4];
    #pragma unroll
    for (int kt = 0; kt < 4; kt++) {
        int r0 = wrow + g, r1 = wrow + g + 8;
        int c0 = kt * 16 + 2 * tig;
        kfh[kt][0] = *(uint32_t*)(KH + r0 * 136 + c0 * 2);
        kfh[kt][1] = *(uint32_t*)(KH + r1 * 136 + c0 * 2);
        kfh[kt][2] = *(uint32_t*)(KH + r0 * 136 + (c0 + 8) * 2);
        kfh[kt][3] = *(uint32_t*)(KH + r1 * 136 + (c0 + 8) * 2);
        kfl[kt][0] = *(uint32_t*)(KL + r0 * 136 + c0 * 2);
        kfl[kt][1] = *(uint32_t*)(KL + r1 * 136 + c0 * 2);
        kfl[kt][2] = *(uint32_t*)(KL + r0 * 136 + (c0 + 8) * 2);
        kfl[kt][3] = *(uint32_t*)(KL + r1 * 136 + (c0 + 8) * 2);
    }

    float o[16][4];
    #pragma unroll
    for (int i = 0; i < 16; i++) { o[i][0] = o[i][1] = o[i][2] = o[i][3] = 0.0f; }
    float rs0 = 0.0f, rs1 = 0.0f;

    for (int t = 0; t < NCHUNK; t++) {
        const int mbase = t * CHUNK;
        __syncthreads();

        {
            const uint32_t* qh = (const uint32_t*)(g_Qhi + (size_t)(b * NN + mbase) * DQ);
            const uint32_t* ql = (const uint32_t*)(g_Qlo + (size_t)(b * NN + mbase) * DQ);
            for (int i = tid; i < 128 * 32; i += 256) {
                int r = i >> 5, c = i & 31;
                *(uint32_t*)(QH + r * 136 + c * 4) = qh[i];
                *(uint32_t*)(QL + r * 136 + c * 4) = ql[i];
            }
        }
        for (int i = tid; i < 128 * 64; i += 256) {
            int d = i >> 6, c = i & 63;
            size_t base = ((size_t)(b * DIN + d)) * NN + mbase;
            *(uint32_t*)(XH + d * 264 + c * 4) = *(const uint32_t*)(g_xThi + base + 2 * c);
            *(uint32_t*)(XL + d * 264 + c * 4) = *(const uint32_t*)(g_xTlo + base + 2 * c);
        }
        if (tid < 128) negp[tid] = (mask[b * NN + mbase + tid] > 0) ? 0.0f : -1e9f;
        __syncthreads();

        #pragma unroll
        for (int j = 0; j < 8; j++) {
            uint32_t pah[4], pal[4];
            #pragma unroll
            for (int h = 0; h < 2; h++) {
                const int nt = 2 * j + h;
                float c4[4] = {0.f, 0.f, 0.f, 0.f};
                const int qr = nt * 8 + g;
                #pragma unroll
                for (int kt = 0; kt < 4; kt++) {
                    const int cc = kt * 16 + 2 * tig;
                    uint32_t bh[2], bl[2];
                    bh[0] = *(uint32_t*)(QH + qr * 136 + cc * 2);
                    bh[1] = *(uint32_t*)(QH + qr * 136 + (cc + 8) * 2);
                    bl[0] = *(uint32_t*)(QL + qr * 136 + cc * 2);
                    bl[1] = *(uint32_t*)(QL + qr * 136 + (cc + 8) * 2);
                    mma16816(c4, kfh[kt], bh);
                    mma16816(c4, kfh[kt], bl);
                    mma16816(c4, kfl[kt], bh);
                }
                const float n0 = negp[nt * 8 + 2 * tig];
                const float n1 = negp[nt * 8 + 2 * tig + 1];
                float p0 = __expf(c4[0] * 0.125f + n0);
                float p1 = __expf(c4[1] * 0.125f + n1);
                float p2 = __expf(c4[2] * 0.125f + n0);
                float p3 = __expf(c4[3] * 0.125f + n1);
                rs0 += p0 + p1;
                rs1 += p2 + p3;
                float h0 = __bfloat162float(__float2bfloat16(p0));
                float h1 = __bfloat162float(__float2bfloat16(p1));
                float h2 = __bfloat162float(__float2bfloat16(p2));
                float h3 = __bfloat162float(__float2bfloat16(p3));
                pah[h * 2 + 0] = pack_bf16(h0, h1);
                pah[h * 2 + 1] = pack_bf16(h2, h3);
                pal[h * 2 + 0] = pack_bf16(p0 - h0, p1 - h1);
                pal[h * 2 + 1] = pack_bf16(p2 - h2, p3 - h3);
            }
            const int q0 = j * 16 + 2 * tig;
            #pragma unroll
            for (int nt2 = 0; nt2 < 16; nt2++) {
                const int xr = nt2 * 8 + g;
                uint32_t bxh[2], bxl[2];
                bxh[0] = *(uint32_t*)(XH + xr * 264 + q0 * 2);
                bxh[1] = *(uint32_t*)(XH + xr * 264 + (q0 + 8) * 2);
                bxl[0] = *(uint32_t*)(XL + xr * 264 + q0 * 2);
                bxl[1] = *(uint32_t*)(XL + xr * 264 + (q0 + 8) * 2);
                mma16816(o[nt2], pah, bxh);
                mma16816(o[nt2], pah, bxl);
                mma16816(o[nt2], pal, bxh);
            }
        }
    }

    rs0 += __shfl_xor_sync(0xffffffffu, rs0, 1);
    rs0 += __shfl_xor_sync(0xffffffffu, rs0, 2);
    rs1 += __shfl_xor_sync(0xffffffffu, rs1, 1);
    rs1 += __shfl_xor_sync(0xffffffffu, rs1, 2);
    const float inv0 = 1.0f / rs0;
    const float inv1 = 1.0f / rs1;

    float* o0p = out + ((size_t)(b * NN + rowbase + wrow + g)) * DIN;
    float* o1p = out + ((size_t)(b * NN + rowbase + wrow + g + 8)) * DIN;
    #pragma unroll
    for (int nt2 = 0; nt2 < 16; nt2++) {
        const int d0 = nt2 * 8 + 2 * tig;
        float2 v0 = make_float2(o[nt2][0] * inv0, o[nt2][1] * inv0);
        float2 v1 = make_float2(o[nt2][2] * inv1, o[nt2][3] * inv1);
        *(float2*)(o0p + d0) = v0;
        *(float2*)(o1p + d0) = v1;
    }
}

// ---------------------------------------------------------------------------
extern "C" void kernel_launch(void* const* d_in, const int* in_sizes, int n_in,
                              void* d_out, int out_size) {
    const float* x  = (const float*)d_in[0];
    const int*   mk = (const int*)d_in[1];
    const float* Wq = (const float*)d_in[2];
    const float* bq = (const float*)d_in[3];
    const float* Wk = (const float*)d_in[4];
    const float* bk = (const float*)d_in[5];
    float* out = (float*)d_out;

    const int proj_smem = (64 * DIN + DIN * 129) * 4;   // 98,816 B
    const int xt_smem   = 64 * 129 * 4;                 // 33,024 B
    const int attn_smem = SA_TOTAL;                     // 137,728 B

    static bool attr_set = false;
    if (!attr_set) {
        cudaFuncSetAttribute(proj_split_kernel, cudaFuncAttributeMaxDynamicSharedMemorySize, proj_smem);
        cudaFuncSetAttribute(xt_split_kernel,   cudaFuncAttributeMaxDynamicSharedMemorySize, xt_smem);
        cudaFuncSetAttribute(attn_mma_kernel,   cudaFuncAttributeMaxDynamicSharedMemorySize, attn_smem);
        attr_set = true;
    }

    proj_split_kernel<<<(BB * NN) / 64, 256, proj_smem>>>(x, Wq, bq, Wk, bk);
    xt_split_kernel<<<dim3(NN / 64, BB), 256, xt_smem>>>(x);
    attn_mma_kernel<<<dim3(NN / 128, BB), 256, attn_smem>>>(mk, out);
}